// round 5
// baseline (speedup 1.0000x reference)
#include <cuda_runtime.h>
#include <cuda_fp16.h>
#include <cstdint>

#define NMAX 100000
#define D 64
#define NBM 8        // msg: nodes per warp-pass (4 pairs)
#define NBU 6        // upd: nodes per warp-pass (3 pairs)

__device__ __half g_m[(size_t)NMAX * D];     // fp16 messages (row = 128B)
__device__ float  g_agg[(size_t)NMAX * D];
__device__ float  g_deg[NMAX];

typedef unsigned long long u64;

__device__ __forceinline__ u64 ffma2(u64 a, u64 b, u64 c) {
    u64 d;
    asm("fma.rn.f32x2 %0, %1, %2, %3;" : "=l"(d) : "l"(a), "l"(b), "l"(c));
    return d;
}
__device__ __forceinline__ u64 pack2(float lo, float hi) {
    u64 d; asm("mov.b64 %0, {%1, %2};" : "=l"(d) : "f"(lo), "f"(hi)); return d;
}
__device__ __forceinline__ void unpack2(u64 v, float& lo, float& hi) {
    asm("mov.b64 {%0, %1}, %2;" : "=f"(lo), "=f"(hi) : "l"(v));
}
__device__ __forceinline__ void red_add_v4(float* addr, float4 v) {
    asm volatile("red.global.add.v4.f32 [%0], {%1, %2, %3, %4};"
                 :: "l"(addr), "f"(v.x), "f"(v.y), "f"(v.z), "f"(v.w) : "memory");
}
__device__ __forceinline__ void red_add_f32(float* addr, float v) {
    asm volatile("red.global.add.f32 [%0], %1;" :: "l"(addr), "f"(v) : "memory");
}

// --------------------------------------------------------------------------
__global__ void zero_kernel(int n) {
    int stride = gridDim.x * blockDim.x;
    int tid = blockIdx.x * blockDim.x + threadIdx.x;
    int total4 = n * (D / 4);
    float4 z = make_float4(0.f, 0.f, 0.f, 0.f);
    for (int i = tid; i < total4; i += stride)
        reinterpret_cast<float4*>(g_agg)[i] = z;
    for (int i = tid; i < n; i += stride)
        g_deg[i] = 0.f;
}

// --------------------------------------------------------------------------
// msg: m = relu(x @ W_msg + b) -> fp16   [N,64], K=64
// Warp: NBM=8 nodes (4 f32x2 node-pairs). lane = output col j (and j+32).
// --------------------------------------------------------------------------
__global__ void __launch_bounds__(256) msg_kernel(
    const float* __restrict__ x, const float* __restrict__ W,
    const float* __restrict__ b, int n)
{
    __shared__ float4     Wq[D / 2][32];            // 16 KB
    __shared__ ulonglong2 xp[8][NBM / 2][D / 2];    // 16 KB

    int tid = threadIdx.x;
    for (int i = tid; i < (D / 2) * 32; i += 256) {
        int k2 = i >> 5, j = i & 31;
        Wq[k2][j] = make_float4(W[(2 * k2) * D + j],     W[(2 * k2) * D + j + 32],
                                W[(2 * k2 + 1) * D + j], W[(2 * k2 + 1) * D + j + 32]);
    }
    __syncthreads();

    int warp = tid >> 5, lane = tid & 31;
    u64 bias0 = pack2(b[lane], b[lane]);
    u64 bias1 = pack2(b[lane + 32], b[lane + 32]);

    int gw = blockIdx.x * 8 + warp;
    int nwp = gridDim.x * 8;

    for (int base = gw * NBM; base < n; base += nwp * NBM) {
#pragma unroll
        for (int p = 0; p < NBM / 2; p++) {
            int A = base + 2 * p, B = A + 1;
            int As = min(A, n - 1), Bs = min(B, n - 1);
            float2 ax = reinterpret_cast<const float2*>(x)[(size_t)As * 32 + lane];
            float2 bx = reinterpret_cast<const float2*>(x)[(size_t)Bs * 32 + lane];
            xp[warp][p][lane] = make_ulonglong2(pack2(ax.x, bx.x), pack2(ax.y, bx.y));
        }
        __syncwarp();

        u64 acc0[NBM / 2], acc1[NBM / 2];
#pragma unroll
        for (int p = 0; p < NBM / 2; p++) { acc0[p] = bias0; acc1[p] = bias1; }

#pragma unroll 8
        for (int k2 = 0; k2 < D / 2; k2++) {
            float4 w = Wq[k2][lane];
            u64 w0a = pack2(w.x, w.x);
            u64 w1a = pack2(w.y, w.y);
            u64 w0b = pack2(w.z, w.z);
            u64 w1b = pack2(w.w, w.w);
#pragma unroll
            for (int p = 0; p < NBM / 2; p++) {
                ulonglong2 xv = xp[warp][p][k2];
                acc0[p] = ffma2(xv.x, w0a, acc0[p]);
                acc1[p] = ffma2(xv.x, w1a, acc1[p]);
                acc0[p] = ffma2(xv.y, w0b, acc0[p]);
                acc1[p] = ffma2(xv.y, w1b, acc1[p]);
            }
        }

#pragma unroll
        for (int p = 0; p < NBM / 2; p++) {
            int A = base + 2 * p, B = A + 1;
            float a0, b0f, a1, b1f;
            unpack2(acc0[p], a0, b0f);
            unpack2(acc1[p], a1, b1f);
            if (A < n) {
                __half* mr = g_m + (size_t)A * D;
                mr[lane]      = __float2half(fmaxf(a0, 0.f));
                mr[lane + 32] = __float2half(fmaxf(a1, 0.f));
            }
            if (B < n) {
                __half* mr = g_m + (size_t)B * D;
                mr[lane]      = __float2half(fmaxf(b0f, 0.f));
                mr[lane + 32] = __float2half(fmaxf(b1f, 0.f));
            }
        }
        __syncwarp();
    }
}

// --------------------------------------------------------------------------
// edge: agg[dst] += float(m[src]) * w ; deg[dst] += 1
// 16 threads/edge; each reads 4 halves (8B, row = single 128B line),
// converts, and issues one red.global.add.v4.f32.
// --------------------------------------------------------------------------
__global__ void __launch_bounds__(256) edge_kernel(
    const int* __restrict__ ei, const float* __restrict__ ew, int E)
{
    int t = blockIdx.x * blockDim.x + threadIdx.x;
    int e = t >> 4, sub = t & 15;
    if (e >= E) return;
    int   src = __ldg(ei + e);
    int   dst = __ldg(ei + E + e);
    float w   = __ldg(ew + e);

    const __half2* mrow = reinterpret_cast<const __half2*>(g_m + (size_t)src * D);
    __half2 h0 = mrow[2 * sub];
    __half2 h1 = mrow[2 * sub + 1];
    float2 f0 = __half22float2(h0);
    float2 f1 = __half22float2(h1);
    red_add_v4(g_agg + (size_t)dst * D + sub * 4,
               make_float4(f0.x * w, f0.y * w, f1.x * w, f1.y * w));
    if (sub == 0) red_add_f32(g_deg + dst, 1.0f);
}

// --------------------------------------------------------------------------
// upd: h = relu([x || agg/deg] @ W_upd + b); out = h / max(||h||,1e-12)
// K=128. NBU=6 nodes (3 pairs) -> smem 56KB -> 4 blocks/SM.
// --------------------------------------------------------------------------
__global__ void __launch_bounds__(256) upd_kernel(
    const float* __restrict__ x, const float* __restrict__ W,
    const float* __restrict__ b, float* __restrict__ out, int n)
{
    __shared__ float4     Wq[D][32];               // 32 KB (64 k2-rows, K=128)
    __shared__ ulonglong2 xp[8][NBU / 2][D];       // 24 KB

    int tid = threadIdx.x;
    for (int i = tid; i < D * 32; i += 256) {
        int k2 = i >> 5, j = i & 31;
        Wq[k2][j] = make_float4(W[(2 * k2) * D + j],     W[(2 * k2) * D + j + 32],
                                W[(2 * k2 + 1) * D + j], W[(2 * k2 + 1) * D + j + 32]);
    }
    __syncthreads();

    int warp = tid >> 5, lane = tid & 31;
    u64 bias0 = pack2(b[lane], b[lane]);
    u64 bias1 = pack2(b[lane + 32], b[lane + 32]);

    int gw = blockIdx.x * 8 + warp;
    int nwp = gridDim.x * 8;

    for (int base = gw * NBU; base < n; base += nwp * NBU) {
#pragma unroll
        for (int p = 0; p < NBU / 2; p++) {
            int A = base + 2 * p, B = A + 1;
            int As = min(A, n - 1), Bs = min(B, n - 1);
            float2 ax = reinterpret_cast<const float2*>(x)[(size_t)As * 32 + lane];
            float2 bx = reinterpret_cast<const float2*>(x)[(size_t)Bs * 32 + lane];
            xp[warp][p][lane] = make_ulonglong2(pack2(ax.x, bx.x), pack2(ax.y, bx.y));
            float iA = 1.0f / fmaxf(g_deg[As], 1.0f);
            float iB = 1.0f / fmaxf(g_deg[Bs], 1.0f);
            float2 aa = reinterpret_cast<const float2*>(g_agg)[(size_t)As * 32 + lane];
            float2 ba = reinterpret_cast<const float2*>(g_agg)[(size_t)Bs * 32 + lane];
            xp[warp][p][32 + lane] =
                make_ulonglong2(pack2(aa.x * iA, ba.x * iB), pack2(aa.y * iA, ba.y * iB));
        }
        __syncwarp();

        u64 acc0[NBU / 2], acc1[NBU / 2];
#pragma unroll
        for (int p = 0; p < NBU / 2; p++) { acc0[p] = bias0; acc1[p] = bias1; }

#pragma unroll 8
        for (int k2 = 0; k2 < D; k2++) {          // 64 k2-steps (K=128)
            float4 w = Wq[k2][lane];
            u64 w0a = pack2(w.x, w.x);
            u64 w1a = pack2(w.y, w.y);
            u64 w0b = pack2(w.z, w.z);
            u64 w1b = pack2(w.w, w.w);
#pragma unroll
            for (int p = 0; p < NBU / 2; p++) {
                ulonglong2 xv = xp[warp][p][k2];
                acc0[p] = ffma2(xv.x, w0a, acc0[p]);
                acc1[p] = ffma2(xv.x, w1a, acc1[p]);
                acc0[p] = ffma2(xv.y, w0b, acc0[p]);
                acc1[p] = ffma2(xv.y, w1b, acc1[p]);
            }
        }

#pragma unroll
        for (int p = 0; p < NBU / 2; p++) {
            int A = base + 2 * p, B = A + 1;
            float a0, b0f, a1, b1f;
            unpack2(acc0[p], a0, b0f);
            unpack2(acc1[p], a1, b1f);
            a0 = fmaxf(a0, 0.f);  a1 = fmaxf(a1, 0.f);
            b0f = fmaxf(b0f, 0.f); b1f = fmaxf(b1f, 0.f);
            float ssA = fmaf(a0, a0, a1 * a1);
            float ssB = fmaf(b0f, b0f, b1f * b1f);
#pragma unroll
            for (int off = 16; off > 0; off >>= 1) {
                ssA += __shfl_xor_sync(0xFFFFFFFF, ssA, off);
                ssB += __shfl_xor_sync(0xFFFFFFFF, ssB, off);
            }
            float invA = 1.0f / fmaxf(sqrtf(ssA), 1e-12f);
            float invB = 1.0f / fmaxf(sqrtf(ssB), 1e-12f);
            if (A < n) {
                float* orow = out + (size_t)A * D;
                orow[lane]      = a0 * invA;
                orow[lane + 32] = a1 * invA;
            }
            if (B < n) {
                float* orow = out + (size_t)B * D;
                orow[lane]      = b0f * invB;
                orow[lane + 32] = b1f * invB;
            }
        }
        __syncwarp();
    }
}

// --------------------------------------------------------------------------
extern "C" void kernel_launch(void* const* d_in, const int* in_sizes, int n_in,
                              void* d_out, int out_size)
{
    const float* x  = (const float*)d_in[0];
    const int*   ei = (const int*)  d_in[1];
    const float* ew = (const float*)d_in[2];
    const float* Wm = (const float*)d_in[3];
    const float* bm = (const float*)d_in[4];
    const float* Wu = (const float*)d_in[5];
    const float* bu = (const float*)d_in[6];
    float* out = (float*)d_out;

    int n = in_sizes[0] / D;       // 100000
    int E = in_sizes[1] / 2;       // 1200000
    if (n > NMAX) n = NMAX;

    zero_kernel<<<1024, 256>>>(n);
    msg_kernel<<<592, 256>>>(x, Wm, bm, n);
    int edge_threads = E * 16;
    edge_kernel<<<(edge_threads + 255) / 256, 256>>>(ei, ew, E);
    upd_kernel<<<592, 256>>>(x, Wu, bu, out, n);
}

// round 6
// speedup vs baseline: 1.2075x; 1.2075x over previous
#include <cuda_runtime.h>
#include <cstdint>

#define NMAX 100000
#define EMAX 1200000
#define D 64
#define NB 8         // nodes per warp-pass (4 pairs) for msg/upd
#define CHUNK 1024

__device__ float g_m[(size_t)NMAX * D];
__device__ float g_agg[(size_t)NMAX * D];
__device__ int   g_cnt[NMAX];
__device__ int   g_off[NMAX];
__device__ int   g_cur[NMAX];
__device__ int   g_part[256];
__device__ int   g_partx[256];
__device__ unsigned long long g_rec[EMAX];

typedef unsigned long long u64;

__device__ __forceinline__ u64 ffma2(u64 a, u64 b, u64 c) {
    u64 d;
    asm("fma.rn.f32x2 %0, %1, %2, %3;" : "=l"(d) : "l"(a), "l"(b), "l"(c));
    return d;
}
__device__ __forceinline__ u64 pack2(float lo, float hi) {
    u64 d; asm("mov.b64 %0, {%1, %2};" : "=l"(d) : "f"(lo), "f"(hi)); return d;
}
__device__ __forceinline__ void unpack2(u64 v, float& lo, float& hi) {
    asm("mov.b64 {%0, %1}, %2;" : "=f"(lo), "=f"(hi) : "l"(v));
}

// ---------------------------------------------------------------- stage 0
__global__ void zero_cnt_kernel(int n) {
    int i = blockIdx.x * blockDim.x + threadIdx.x;
    if (i < n) g_cnt[i] = 0;
}

// ---------------------------------------------------------------- stage 1
// msg: m = relu(x @ W_msg + b)  [N,64] fp32, NB=8 nodes/warp, f32x2 FMA.
__global__ void __launch_bounds__(256) msg_kernel(
    const float* __restrict__ x, const float* __restrict__ W,
    const float* __restrict__ b, int n)
{
    __shared__ float4     Wq[D / 2][32];          // 16 KB
    __shared__ ulonglong2 xp[8][NB / 2][D / 2];   // 16 KB

    int tid = threadIdx.x;
    for (int i = tid; i < (D / 2) * 32; i += 256) {
        int k2 = i >> 5, j = i & 31;
        Wq[k2][j] = make_float4(W[(2 * k2) * D + j],     W[(2 * k2) * D + j + 32],
                                W[(2 * k2 + 1) * D + j], W[(2 * k2 + 1) * D + j + 32]);
    }
    __syncthreads();

    int warp = tid >> 5, lane = tid & 31;
    u64 bias0 = pack2(b[lane], b[lane]);
    u64 bias1 = pack2(b[lane + 32], b[lane + 32]);

    int gw = blockIdx.x * 8 + warp;
    int nwp = gridDim.x * 8;

    for (int base = gw * NB; base < n; base += nwp * NB) {
#pragma unroll
        for (int p = 0; p < NB / 2; p++) {
            int A = base + 2 * p, B = A + 1;
            int As = min(A, n - 1), Bs = min(B, n - 1);
            float2 ax = reinterpret_cast<const float2*>(x)[(size_t)As * 32 + lane];
            float2 bx = reinterpret_cast<const float2*>(x)[(size_t)Bs * 32 + lane];
            xp[warp][p][lane] = make_ulonglong2(pack2(ax.x, bx.x), pack2(ax.y, bx.y));
        }
        __syncwarp();

        u64 acc0[NB / 2], acc1[NB / 2];
#pragma unroll
        for (int p = 0; p < NB / 2; p++) { acc0[p] = bias0; acc1[p] = bias1; }

#pragma unroll 8
        for (int k2 = 0; k2 < D / 2; k2++) {
            float4 w = Wq[k2][lane];
            u64 w0a = pack2(w.x, w.x);
            u64 w1a = pack2(w.y, w.y);
            u64 w0b = pack2(w.z, w.z);
            u64 w1b = pack2(w.w, w.w);
#pragma unroll
            for (int p = 0; p < NB / 2; p++) {
                ulonglong2 xv = xp[warp][p][k2];
                acc0[p] = ffma2(xv.x, w0a, acc0[p]);
                acc1[p] = ffma2(xv.x, w1a, acc1[p]);
                acc0[p] = ffma2(xv.y, w0b, acc0[p]);
                acc1[p] = ffma2(xv.y, w1b, acc1[p]);
            }
        }

#pragma unroll
        for (int p = 0; p < NB / 2; p++) {
            int A = base + 2 * p, B = A + 1;
            float a0, b0f, a1, b1f;
            unpack2(acc0[p], a0, b0f);
            unpack2(acc1[p], a1, b1f);
            if (A < n) {
                float* mr = g_m + (size_t)A * D;
                mr[lane]      = fmaxf(a0, 0.f);
                mr[lane + 32] = fmaxf(a1, 0.f);
            }
            if (B < n) {
                float* mr = g_m + (size_t)B * D;
                mr[lane]      = fmaxf(b0f, 0.f);
                mr[lane + 32] = fmaxf(b1f, 0.f);
            }
        }
        __syncwarp();
    }
}

// ---------------------------------------------------------------- stage 2
__global__ void hist_kernel(const int* __restrict__ ei, int E) {
    int e = blockIdx.x * blockDim.x + threadIdx.x;
    if (e < E) atomicAdd(&g_cnt[ei[E + e]], 1);
}

// ---------------------------------------------------------------- stage 3: scan
__global__ void scan_partial_kernel(int n) {
    __shared__ int s[CHUNK];
    int t = threadIdx.x;
    int i = blockIdx.x * CHUNK + t;
    s[t] = (i < n) ? g_cnt[i] : 0;
    __syncthreads();
    for (int d = CHUNK / 2; d > 0; d >>= 1) {
        if (t < d) s[t] += s[t + d];
        __syncthreads();
    }
    if (t == 0) g_part[blockIdx.x] = s[0];
}

__global__ void scan_mid_kernel(int nchunks) {
    __shared__ int s[256];
    int t = threadIdx.x;
    int v = (t < nchunks) ? g_part[t] : 0;
    s[t] = v;
    __syncthreads();
    for (int d = 1; d < 256; d <<= 1) {
        int add = (t >= d) ? s[t - d] : 0;
        __syncthreads();
        s[t] += add;
        __syncthreads();
    }
    if (t < nchunks) g_partx[t] = s[t] - v;   // exclusive
}

__global__ void scan_final_kernel(int n) {
    __shared__ int s[CHUNK];
    int t = threadIdx.x;
    int i = blockIdx.x * CHUNK + t;
    int v = (i < n) ? g_cnt[i] : 0;
    s[t] = v;
    __syncthreads();
    for (int d = 1; d < CHUNK; d <<= 1) {
        int add = (t >= d) ? s[t - d] : 0;
        __syncthreads();
        s[t] += add;
        __syncthreads();
    }
    if (i < n) {
        int excl = s[t] - v + g_partx[blockIdx.x];
        g_off[i] = excl;
        g_cur[i] = excl;
    }
}

// ---------------------------------------------------------------- stage 4
__global__ void scatter_kernel(const int* __restrict__ ei,
                               const float* __restrict__ ew, int E) {
    int e = blockIdx.x * blockDim.x + threadIdx.x;
    if (e >= E) return;
    int src = ei[e];
    int dst = ei[E + e];
    float w = ew[e];
    int pos = atomicAdd(&g_cur[dst], 1);
    g_rec[pos] = ((u64)__float_as_uint(w) << 32) | (unsigned)src;
}

// ---------------------------------------------------------------- stage 5
// agg[node] = (1/max(deg,1)) * sum_{edges->node} w * m[src]
// 16 lanes per node; register accumulation; single write.
__global__ void __launch_bounds__(256) gather_kernel(int n) {
    int t = blockIdx.x * blockDim.x + threadIdx.x;
    int node = t >> 4;
    int lane16 = t & 15;
    if (node >= n) return;

    int start = g_off[node];
    int deg   = g_cnt[node];

    const float4* m4 = reinterpret_cast<const float4*>(g_m);
    float4 acc = make_float4(0.f, 0.f, 0.f, 0.f);

    u64 r = (deg > 0) ? g_rec[start] : 0ULL;
    for (int j = 0; j < deg; j++) {
        u64 rn = (j + 1 < deg) ? g_rec[start + j + 1] : 0ULL;   // prefetch
        int   src = (int)(unsigned)(r & 0xffffffffULL);
        float w   = __uint_as_float((unsigned)(r >> 32));
        float4 mv = m4[(size_t)src * 16 + lane16];
        acc.x = fmaf(w, mv.x, acc.x);
        acc.y = fmaf(w, mv.y, acc.y);
        acc.z = fmaf(w, mv.z, acc.z);
        acc.w = fmaf(w, mv.w, acc.w);
        r = rn;
    }
    float inv = 1.0f / (float)max(deg, 1);
    reinterpret_cast<float4*>(g_agg)[(size_t)node * 16 + lane16] =
        make_float4(acc.x * inv, acc.y * inv, acc.z * inv, acc.w * inv);
}

// ---------------------------------------------------------------- stage 6
// upd: h = relu([x || agg] @ W_upd + b); out = h / max(||h||,1e-12)
// (agg is already mean-normalized). NB=8, smem 64 KB — R4 config.
__global__ void __launch_bounds__(256) upd_kernel(
    const float* __restrict__ x, const float* __restrict__ W,
    const float* __restrict__ b, float* __restrict__ out, int n)
{
    __shared__ float4     Wq[D][32];               // 32 KB
    __shared__ ulonglong2 xp[8][NB / 2][D];        // 32 KB

    int tid = threadIdx.x;
    for (int i = tid; i < D * 32; i += 256) {
        int k2 = i >> 5, j = i & 31;
        Wq[k2][j] = make_float4(W[(2 * k2) * D + j],     W[(2 * k2) * D + j + 32],
                                W[(2 * k2 + 1) * D + j], W[(2 * k2 + 1) * D + j + 32]);
    }
    __syncthreads();

    int warp = tid >> 5, lane = tid & 31;
    u64 bias0 = pack2(b[lane], b[lane]);
    u64 bias1 = pack2(b[lane + 32], b[lane + 32]);

    int gw = blockIdx.x * 8 + warp;
    int nwp = gridDim.x * 8;

    for (int base = gw * NB; base < n; base += nwp * NB) {
#pragma unroll
        for (int p = 0; p < NB / 2; p++) {
            int A = base + 2 * p, B = A + 1;
            int As = min(A, n - 1), Bs = min(B, n - 1);
            float2 ax = reinterpret_cast<const float2*>(x)[(size_t)As * 32 + lane];
            float2 bx = reinterpret_cast<const float2*>(x)[(size_t)Bs * 32 + lane];
            xp[warp][p][lane] = make_ulonglong2(pack2(ax.x, bx.x), pack2(ax.y, bx.y));
            float2 aa = reinterpret_cast<const float2*>(g_agg)[(size_t)As * 32 + lane];
            float2 ba = reinterpret_cast<const float2*>(g_agg)[(size_t)Bs * 32 + lane];
            xp[warp][p][32 + lane] =
                make_ulonglong2(pack2(aa.x, ba.x), pack2(aa.y, ba.y));
        }
        __syncwarp();

        u64 acc0[NB / 2], acc1[NB / 2];
#pragma unroll
        for (int p = 0; p < NB / 2; p++) { acc0[p] = bias0; acc1[p] = bias1; }

#pragma unroll 8
        for (int k2 = 0; k2 < D; k2++) {          // 64 k2-steps (K=128)
            float4 w = Wq[k2][lane];
            u64 w0a = pack2(w.x, w.x);
            u64 w1a = pack2(w.y, w.y);
            u64 w0b = pack2(w.z, w.z);
            u64 w1b = pack2(w.w, w.w);
#pragma unroll
            for (int p = 0; p < NB / 2; p++) {
                ulonglong2 xv = xp[warp][p][k2];
                acc0[p] = ffma2(xv.x, w0a, acc0[p]);
                acc1[p] = ffma2(xv.x, w1a, acc1[p]);
                acc0[p] = ffma2(xv.y, w0b, acc0[p]);
                acc1[p] = ffma2(xv.y, w1b, acc1[p]);
            }
        }

#pragma unroll
        for (int p = 0; p < NB / 2; p++) {
            int A = base + 2 * p, B = A + 1;
            float a0, b0f, a1, b1f;
            unpack2(acc0[p], a0, b0f);
            unpack2(acc1[p], a1, b1f);
            a0 = fmaxf(a0, 0.f);   a1 = fmaxf(a1, 0.f);
            b0f = fmaxf(b0f, 0.f); b1f = fmaxf(b1f, 0.f);
            float ssA = fmaf(a0, a0, a1 * a1);
            float ssB = fmaf(b0f, b0f, b1f * b1f);
#pragma unroll
            for (int off = 16; off > 0; off >>= 1) {
                ssA += __shfl_xor_sync(0xFFFFFFFF, ssA, off);
                ssB += __shfl_xor_sync(0xFFFFFFFF, ssB, off);
            }
            float invA = 1.0f / fmaxf(sqrtf(ssA), 1e-12f);
            float invB = 1.0f / fmaxf(sqrtf(ssB), 1e-12f);
            if (A < n) {
                float* orow = out + (size_t)A * D;
                orow[lane]      = a0 * invA;
                orow[lane + 32] = a1 * invA;
            }
            if (B < n) {
                float* orow = out + (size_t)B * D;
                orow[lane]      = b0f * invB;
                orow[lane + 32] = b1f * invB;
            }
        }
        __syncwarp();
    }
}

// --------------------------------------------------------------------------
extern "C" void kernel_launch(void* const* d_in, const int* in_sizes, int n_in,
                              void* d_out, int out_size)
{
    const float* x  = (const float*)d_in[0];
    const int*   ei = (const int*)  d_in[1];
    const float* ew = (const float*)d_in[2];
    const float* Wm = (const float*)d_in[3];
    const float* bm = (const float*)d_in[4];
    const float* Wu = (const float*)d_in[5];
    const float* bu = (const float*)d_in[6];
    float* out = (float*)d_out;

    int n = in_sizes[0] / D;       // 100000
    int E = in_sizes[1] / 2;       // 1200000
    if (n > NMAX) n = NMAX;
    if (E > EMAX) E = EMAX;

    int nchunks = (n + CHUNK - 1) / CHUNK;        // 98

    zero_cnt_kernel<<<(n + 255) / 256, 256>>>(n);
    msg_kernel<<<592, 256>>>(x, Wm, bm, n);
    hist_kernel<<<(E + 255) / 256, 256>>>(ei, E);
    scan_partial_kernel<<<nchunks, CHUNK>>>(n);
    scan_mid_kernel<<<1, 256>>>(nchunks);
    scan_final_kernel<<<nchunks, CHUNK>>>(n);
    scatter_kernel<<<(E + 255) / 256, 256>>>(ei, ew, E);
    gather_kernel<<<(n * 16 + 255) / 256, 256>>>(n);
    upd_kernel<<<444, 256>>>(x, Wu, bu, out, n);
}

// round 7
// speedup vs baseline: 1.2842x; 1.0635x over previous
#include <cuda_runtime.h>
#include <cuda_fp16.h>
#include <cstdint>

#define NMAX 100000
#define EMAX 1200000
#define D 64
#define NB 8         // nodes per warp-pass (4 pairs) for msg/upd
#define CHUNK 1024

__device__ __half g_m[(size_t)NMAX * D];     // fp16 messages: row = 128 B
__device__ float  g_agg[(size_t)NMAX * D];
__device__ int    g_cnt[NMAX];
__device__ int    g_off[NMAX];
__device__ int    g_cur[NMAX];
__device__ int    g_part[256];
__device__ int    g_partx[256];
__device__ unsigned long long g_rec[EMAX];

typedef unsigned long long u64;

__device__ __forceinline__ u64 ffma2(u64 a, u64 b, u64 c) {
    u64 d;
    asm("fma.rn.f32x2 %0, %1, %2, %3;" : "=l"(d) : "l"(a), "l"(b), "l"(c));
    return d;
}
__device__ __forceinline__ u64 pack2(float lo, float hi) {
    u64 d; asm("mov.b64 %0, {%1, %2};" : "=l"(d) : "f"(lo), "f"(hi)); return d;
}
__device__ __forceinline__ void unpack2(u64 v, float& lo, float& hi) {
    asm("mov.b64 {%0, %1}, %2;" : "=f"(lo), "=f"(hi) : "l"(v));
}

// ---------------------------------------------------------------- stage 0
__global__ void zero_cnt_kernel(int n) {
    int i = blockIdx.x * blockDim.x + threadIdx.x;
    if (i < n) g_cnt[i] = 0;
}

// ---------------------------------------------------------------- stage 1
// msg: m = relu(x @ W_msg + b)  [N,64] -> fp16, NB=8 nodes/warp, f32x2 FMA.
__global__ void __launch_bounds__(256) msg_kernel(
    const float* __restrict__ x, const float* __restrict__ W,
    const float* __restrict__ b, int n)
{
    __shared__ float4     Wq[D / 2][32];          // 16 KB
    __shared__ ulonglong2 xp[8][NB / 2][D / 2];   // 16 KB

    int tid = threadIdx.x;
    for (int i = tid; i < (D / 2) * 32; i += 256) {
        int k2 = i >> 5, j = i & 31;
        Wq[k2][j] = make_float4(W[(2 * k2) * D + j],     W[(2 * k2) * D + j + 32],
                                W[(2 * k2 + 1) * D + j], W[(2 * k2 + 1) * D + j + 32]);
    }
    __syncthreads();

    int warp = tid >> 5, lane = tid & 31;
    u64 bias0 = pack2(b[lane], b[lane]);
    u64 bias1 = pack2(b[lane + 32], b[lane + 32]);

    int gw = blockIdx.x * 8 + warp;
    int nwp = gridDim.x * 8;

    for (int base = gw * NB; base < n; base += nwp * NB) {
#pragma unroll
        for (int p = 0; p < NB / 2; p++) {
            int A = base + 2 * p, B = A + 1;
            int As = min(A, n - 1), Bs = min(B, n - 1);
            float2 ax = reinterpret_cast<const float2*>(x)[(size_t)As * 32 + lane];
            float2 bx = reinterpret_cast<const float2*>(x)[(size_t)Bs * 32 + lane];
            xp[warp][p][lane] = make_ulonglong2(pack2(ax.x, bx.x), pack2(ax.y, bx.y));
        }
        __syncwarp();

        u64 acc0[NB / 2], acc1[NB / 2];
#pragma unroll
        for (int p = 0; p < NB / 2; p++) { acc0[p] = bias0; acc1[p] = bias1; }

#pragma unroll 8
        for (int k2 = 0; k2 < D / 2; k2++) {
            float4 w = Wq[k2][lane];
            u64 w0a = pack2(w.x, w.x);
            u64 w1a = pack2(w.y, w.y);
            u64 w0b = pack2(w.z, w.z);
            u64 w1b = pack2(w.w, w.w);
#pragma unroll
            for (int p = 0; p < NB / 2; p++) {
                ulonglong2 xv = xp[warp][p][k2];
                acc0[p] = ffma2(xv.x, w0a, acc0[p]);
                acc1[p] = ffma2(xv.x, w1a, acc1[p]);
                acc0[p] = ffma2(xv.y, w0b, acc0[p]);
                acc1[p] = ffma2(xv.y, w1b, acc1[p]);
            }
        }

#pragma unroll
        for (int p = 0; p < NB / 2; p++) {
            int A = base + 2 * p, B = A + 1;
            float a0, b0f, a1, b1f;
            unpack2(acc0[p], a0, b0f);
            unpack2(acc1[p], a1, b1f);
            if (A < n) {
                __half* mr = g_m + (size_t)A * D;
                mr[lane]      = __float2half(fmaxf(a0, 0.f));
                mr[lane + 32] = __float2half(fmaxf(a1, 0.f));
            }
            if (B < n) {
                __half* mr = g_m + (size_t)B * D;
                mr[lane]      = __float2half(fmaxf(b0f, 0.f));
                mr[lane + 32] = __float2half(fmaxf(b1f, 0.f));
            }
        }
        __syncwarp();
    }
}

// ---------------------------------------------------------------- stage 2
__global__ void hist_kernel(const int* __restrict__ ei, int E) {
    int e = blockIdx.x * blockDim.x + threadIdx.x;
    if (e < E) atomicAdd(&g_cnt[ei[E + e]], 1);
}

// ---------------------------------------------------------------- stage 3: scan
__global__ void scan_partial_kernel(int n) {
    __shared__ int s[CHUNK];
    int t = threadIdx.x;
    int i = blockIdx.x * CHUNK + t;
    s[t] = (i < n) ? g_cnt[i] : 0;
    __syncthreads();
    for (int d = CHUNK / 2; d > 0; d >>= 1) {
        if (t < d) s[t] += s[t + d];
        __syncthreads();
    }
    if (t == 0) g_part[blockIdx.x] = s[0];
}

__global__ void scan_mid_kernel(int nchunks) {
    __shared__ int s[256];
    int t = threadIdx.x;
    int v = (t < nchunks) ? g_part[t] : 0;
    s[t] = v;
    __syncthreads();
    for (int d = 1; d < 256; d <<= 1) {
        int add = (t >= d) ? s[t - d] : 0;
        __syncthreads();
        s[t] += add;
        __syncthreads();
    }
    if (t < nchunks) g_partx[t] = s[t] - v;   // exclusive
}

__global__ void scan_final_kernel(int n) {
    __shared__ int s[CHUNK];
    int t = threadIdx.x;
    int i = blockIdx.x * CHUNK + t;
    int v = (i < n) ? g_cnt[i] : 0;
    s[t] = v;
    __syncthreads();
    for (int d = 1; d < CHUNK; d <<= 1) {
        int add = (t >= d) ? s[t - d] : 0;
        __syncthreads();
        s[t] += add;
        __syncthreads();
    }
    if (i < n) {
        int excl = s[t] - v + g_partx[blockIdx.x];
        g_off[i] = excl;
        g_cur[i] = excl;
    }
}

// ---------------------------------------------------------------- stage 4
__global__ void scatter_kernel(const int* __restrict__ ei,
                               const float* __restrict__ ew, int E) {
    int e = blockIdx.x * blockDim.x + threadIdx.x;
    if (e >= E) return;
    int src = ei[e];
    int dst = ei[E + e];
    float w = ew[e];
    int pos = atomicAdd(&g_cur[dst], 1);
    g_rec[pos] = ((u64)__float_as_uint(w) << 32) | (unsigned)src;
}

// ---------------------------------------------------------------- stage 5
// agg[node] = (1/max(deg,1)) * sum w * m[src]  (m fp16, fp32 accumulate)
// 8 lanes per node; each lane owns 8 cols (one 16B half8 load per edge).
__global__ void __launch_bounds__(256) gather_kernel(int n) {
    int t = blockIdx.x * blockDim.x + threadIdx.x;
    int node  = t >> 3;
    int lane8 = t & 7;
    if (node >= n) return;

    int start = g_off[node];
    int deg   = g_cnt[node];

    const float4* m4 = reinterpret_cast<const float4*>(g_m);  // 16B = 8 halves
    float acc[8];
#pragma unroll
    for (int c = 0; c < 8; c++) acc[c] = 0.f;

    u64 r = (deg > 0) ? g_rec[start] : 0ULL;
    for (int j = 0; j < deg; j++) {
        u64 rn = (j + 1 < deg) ? g_rec[start + j + 1] : 0ULL;   // prefetch
        int   src = (int)(unsigned)(r & 0xffffffffULL);
        float w   = __uint_as_float((unsigned)(r >> 32));
        float4 raw = m4[(size_t)src * 8 + lane8];
        const __half2* hp = reinterpret_cast<const __half2*>(&raw);
#pragma unroll
        for (int q = 0; q < 4; q++) {
            float2 f = __half22float2(hp[q]);
            acc[2 * q]     = fmaf(w, f.x, acc[2 * q]);
            acc[2 * q + 1] = fmaf(w, f.y, acc[2 * q + 1]);
        }
        r = rn;
    }
    float inv = 1.0f / (float)max(deg, 1);
    float4* ar = reinterpret_cast<float4*>(g_agg + (size_t)node * D + lane8 * 8);
    ar[0] = make_float4(acc[0] * inv, acc[1] * inv, acc[2] * inv, acc[3] * inv);
    ar[1] = make_float4(acc[4] * inv, acc[5] * inv, acc[6] * inv, acc[7] * inv);
}

// ---------------------------------------------------------------- stage 6
// upd: h = relu([x || agg] @ W_upd + b); out = h / max(||h||,1e-12)
// (agg already mean-normalized). NB=8, smem 64 KB.
__global__ void __launch_bounds__(256) upd_kernel(
    const float* __restrict__ x, const float* __restrict__ W,
    const float* __restrict__ b, float* __restrict__ out, int n)
{
    __shared__ float4     Wq[D][32];               // 32 KB
    __shared__ ulonglong2 xp[8][NB / 2][D];        // 32 KB

    int tid = threadIdx.x;
    for (int i = tid; i < D * 32; i += 256) {
        int k2 = i >> 5, j = i & 31;
        Wq[k2][j] = make_float4(W[(2 * k2) * D + j],     W[(2 * k2) * D + j + 32],
                                W[(2 * k2 + 1) * D + j], W[(2 * k2 + 1) * D + j + 32]);
    }
    __syncthreads();

    int warp = tid >> 5, lane = tid & 31;
    u64 bias0 = pack2(b[lane], b[lane]);
    u64 bias1 = pack2(b[lane + 32], b[lane + 32]);

    int gw = blockIdx.x * 8 + warp;
    int nwp = gridDim.x * 8;

    for (int base = gw * NB; base < n; base += nwp * NB) {
#pragma unroll
        for (int p = 0; p < NB / 2; p++) {
            int A = base + 2 * p, B = A + 1;
            int As = min(A, n - 1), Bs = min(B, n - 1);
            float2 ax = reinterpret_cast<const float2*>(x)[(size_t)As * 32 + lane];
            float2 bx = reinterpret_cast<const float2*>(x)[(size_t)Bs * 32 + lane];
            xp[warp][p][lane] = make_ulonglong2(pack2(ax.x, bx.x), pack2(ax.y, bx.y));
            float2 aa = reinterpret_cast<const float2*>(g_agg)[(size_t)As * 32 + lane];
            float2 ba = reinterpret_cast<const float2*>(g_agg)[(size_t)Bs * 32 + lane];
            xp[warp][p][32 + lane] =
                make_ulonglong2(pack2(aa.x, ba.x), pack2(aa.y, ba.y));
        }
        __syncwarp();

        u64 acc0[NB / 2], acc1[NB / 2];
#pragma unroll
        for (int p = 0; p < NB / 2; p++) { acc0[p] = bias0; acc1[p] = bias1; }

#pragma unroll 8
        for (int k2 = 0; k2 < D; k2++) {          // 64 k2-steps (K=128)
            float4 w = Wq[k2][lane];
            u64 w0a = pack2(w.x, w.x);
            u64 w1a = pack2(w.y, w.y);
            u64 w0b = pack2(w.z, w.z);
            u64 w1b = pack2(w.w, w.w);
#pragma unroll
            for (int p = 0; p < NB / 2; p++) {
                ulonglong2 xv = xp[warp][p][k2];
                acc0[p] = ffma2(xv.x, w0a, acc0[p]);
                acc1[p] = ffma2(xv.x, w1a, acc1[p]);
                acc0[p] = ffma2(xv.y, w0b, acc0[p]);
                acc1[p] = ffma2(xv.y, w1b, acc1[p]);
            }
        }

#pragma unroll
        for (int p = 0; p < NB / 2; p++) {
            int A = base + 2 * p, B = A + 1;
            float a0, b0f, a1, b1f;
            unpack2(acc0[p], a0, b0f);
            unpack2(acc1[p], a1, b1f);
            a0 = fmaxf(a0, 0.f);   a1 = fmaxf(a1, 0.f);
            b0f = fmaxf(b0f, 0.f); b1f = fmaxf(b1f, 0.f);
            float ssA = fmaf(a0, a0, a1 * a1);
            float ssB = fmaf(b0f, b0f, b1f * b1f);
#pragma unroll
            for (int off = 16; off > 0; off >>= 1) {
                ssA += __shfl_xor_sync(0xFFFFFFFF, ssA, off);
                ssB += __shfl_xor_sync(0xFFFFFFFF, ssB, off);
            }
            float invA = 1.0f / fmaxf(sqrtf(ssA), 1e-12f);
            float invB = 1.0f / fmaxf(sqrtf(ssB), 1e-12f);
            if (A < n) {
                float* orow = out + (size_t)A * D;
                orow[lane]      = a0 * invA;
                orow[lane + 32] = a1 * invA;
            }
            if (B < n) {
                float* orow = out + (size_t)B * D;
                orow[lane]      = b0f * invB;
                orow[lane + 32] = b1f * invB;
            }
        }
        __syncwarp();
    }
}

// --------------------------------------------------------------------------
extern "C" void kernel_launch(void* const* d_in, const int* in_sizes, int n_in,
                              void* d_out, int out_size)
{
    const float* x  = (const float*)d_in[0];
    const int*   ei = (const int*)  d_in[1];
    const float* ew = (const float*)d_in[2];
    const float* Wm = (const float*)d_in[3];
    const float* bm = (const float*)d_in[4];
    const float* Wu = (const float*)d_in[5];
    const float* bu = (const float*)d_in[6];
    float* out = (float*)d_out;

    int n = in_sizes[0] / D;       // 100000
    int E = in_sizes[1] / 2;       // 1200000
    if (n > NMAX) n = NMAX;
    if (E > EMAX) E = EMAX;

    int nchunks = (n + CHUNK - 1) / CHUNK;        // 98

    zero_cnt_kernel<<<(n + 255) / 256, 256>>>(n);
    msg_kernel<<<592, 256>>>(x, Wm, bm, n);
    hist_kernel<<<(E + 255) / 256, 256>>>(ei, E);
    scan_partial_kernel<<<nchunks, CHUNK>>>(n);
    scan_mid_kernel<<<1, 256>>>(nchunks);
    scan_final_kernel<<<nchunks, CHUNK>>>(n);
    scatter_kernel<<<(E + 255) / 256, 256>>>(ei, ew, E);
    gather_kernel<<<(n * 8 + 255) / 256, 256>>>(n);
    upd_kernel<<<444, 256>>>(x, Wu, bu, out, n);
}